// round 8
// baseline (speedup 1.0000x reference)
#include <cuda_runtime.h>
#include <math.h>

#define NB 32
#define NN 1024
#define L2E 1.4426950408889634f
#define RPC 16                 // rows per CTA
#define CPB 64                 // CTAs per batch (1024/16)
#define SLOTS 4                // concurrent batch slots
#define BPS 8                  // batches per slot (32/4)
#define THREADS 512
#define ITERS 20

// Cumulative column sums (per batch), barrier state. Barrier generation is
// monotone across graph replays (equality-compare => any start value is fine);
// counters self-reset; colacc is re-zeroed by init_kernel each launch.
__device__ float    d_colacc[NB][NN];
__device__ unsigned d_bar_cnt[NB];
__device__ unsigned d_bar_gen[NB];

// ---------------------------------------------------------------------------
__global__ __launch_bounds__(512) void init_kernel() {
    ((float*)d_colacc)[blockIdx.x * 512 + threadIdx.x] = 0.0f;
}

// ---------------------------------------------------------------------------
// 64-CTA per-batch barrier. Safe because grid(256) <= residency capacity(296).
__device__ __forceinline__ void batch_bar(int b) {
    __syncthreads();
    if (threadIdx.x == 0) {
        __threadfence();                       // publish colacc REDs
        unsigned gen = *(volatile unsigned*)&d_bar_gen[b];
        unsigned a   = atomicAdd(&d_bar_cnt[b], 1u);
        if (a == CPB - 1) {
            atomicExch(&d_bar_cnt[b], 0u);
            __threadfence();
            atomicAdd(&d_bar_gen[b], 1u);
        } else {
            while (*(volatile unsigned*)&d_bar_gen[b] == gen) __nanosleep(32);
        }
        __threadfence();                       // acquire colacc values
    }
    __syncthreads();
}

// ---------------------------------------------------------------------------
// Persistent Sinkhorn. Slot s = blockIdx.x/64 processes batches s, s+4, ...
// Per iteration per CTA (16 rows of one batch):
//   fold:   C_j -= log2(colacc_j - prev_j); prev_j = colacc_j      (k>0)
//   rows:   E_ij = exp2(g*L2E + C_j) -> smem; rowsum -> inv_i
//   cols:   atomicAdd(colacc_j, sum_i E_ij * inv_i)   [cumulative]
//   barrier(batch)
// Final:  out_ij = E_ij * inv_i / (colacc_j - prev_j)   (E still in smem)
__global__ __launch_bounds__(THREADS, 2)
void sinkhorn_persistent(const float* __restrict__ g, float* __restrict__ out) {
    extern __shared__ float smem[];
    float* s_E    = smem;                    // RPC*NN
    float* s_C    = smem + RPC * NN;         // NN
    float* s_prev = s_C + NN;                // NN
    float* s_inv  = s_prev + NN;             // RPC

    const int tid  = threadIdx.x;
    const int slot = blockIdx.x >> 6;
    const int cib  = blockIdx.x & 63;
    const int warp = tid >> 5;
    const int lane = tid & 31;

    for (int bi = 0; bi < BPS; bi++) {
        const int b = slot + bi * SLOTS;
        float* acc_b = d_colacc[b];

        s_C[tid] = 0.0f;  s_C[tid + 512] = 0.0f;
        s_prev[tid] = 0.0f;  s_prev[tid + 512] = 0.0f;
        __syncthreads();

        const int row = (b << 10) + cib * RPC + warp;
        const float4* gr = (const float4*)(g + (size_t)row * NN);
        float4*       er = (float4*)(s_E + warp * NN);
        const float4* c4 = (const float4*)s_C;

        float inv_last = 0.0f;

        for (int k = 0; k < ITERS; k++) {
            if (k > 0) {
#pragma unroll
                for (int t = tid; t < NN; t += 512) {
                    float cum = __ldcg(&acc_b[t]);          // L2, bypass L1
                    s_C[t] -= log2f(cum - s_prev[t]);
                    s_prev[t] = cum;
                }
                __syncthreads();
            }

            // ---- row phase: warp per row ----
            float acc = 0.0f;
#pragma unroll
            for (int kk = 0; kk < 8; kk++) {
                const int idx = lane + 32 * kk;
                const float4 gv = gr[idx];
                const float4 cv = c4[idx];
                float4 e;
                e.x = exp2f(fmaf(gv.x, L2E, cv.x));
                e.y = exp2f(fmaf(gv.y, L2E, cv.y));
                e.z = exp2f(fmaf(gv.z, L2E, cv.z));
                e.w = exp2f(fmaf(gv.w, L2E, cv.w));
                er[idx] = e;
                acc += (e.x + e.y) + (e.z + e.w);
            }
#pragma unroll
            for (int o = 16; o; o >>= 1)
                acc += __shfl_xor_sync(0xffffffffu, acc, o);

            const float inv = __fdividef(1.0f, acc);        // all lanes
            if (lane == 0) s_inv[warp] = inv;
            inv_last = inv;
            __syncthreads();

            // ---- column partials: thread per 2 columns ----
            float iv[RPC];
#pragma unroll
            for (int i = 0; i < RPC; i++) iv[i] = s_inv[i];

            float cx = 0.0f, cy = 0.0f;
#pragma unroll
            for (int i = 0; i < RPC; i++) {
                const float2 ev = ((const float2*)(s_E + i * NN))[tid];
                cx = fmaf(ev.x, iv[i], cx);
                cy = fmaf(ev.y, iv[i], cy);
            }
            atomicAdd(&acc_b[2 * tid],     cx);
            atomicAdd(&acc_b[2 * tid + 1], cy);

            batch_bar(b);
        }

        // ---- final: out = E * inv_i / S_j, E hot in smem ----
#pragma unroll
        for (int t = tid; t < NN; t += 512) {
            const float cum = __ldcg(&acc_b[t]);
            s_C[t] = __fdividef(1.0f, cum - s_prev[t]);     // 1/S_j
        }
        __syncthreads();

        float4* orw = (float4*)(out + (size_t)row * NN);
#pragma unroll
        for (int kk = 0; kk < 8; kk++) {
            const int idx = lane + 32 * kk;
            const float4 e = er[idx];
            const float4 s = c4[idx];
            float4 o;
            o.x = e.x * inv_last * s.x;
            o.y = e.y * inv_last * s.y;
            o.z = e.z * inv_last * s.z;
            o.w = e.w * inv_last * s.w;
            orw[idx] = o;
        }
        __syncthreads();   // protect s_C/s_prev reuse for next batch
    }
}

// ---------------------------------------------------------------------------
extern "C" void kernel_launch(void* const* d_in, const int* in_sizes, int n_in,
                              void* d_out, int out_size) {
    // Only the gumbel tensor matters (score projection cancels in the first
    // row normalization).
    const float* g = nullptr;
    for (int i = 0; i < n_in; i++)
        if (in_sizes[i] == NB * NN * NN) g = (const float*)d_in[i];
    float* out = (float*)d_out;

    const int SMEM_BYTES = (RPC * NN + 2 * NN + RPC) * (int)sizeof(float);
    cudaFuncSetAttribute(sinkhorn_persistent,
                         cudaFuncAttributeMaxDynamicSharedMemorySize, SMEM_BYTES);

    init_kernel<<<NB * NN / 512, 512>>>();   // re-zero colacc each replay
    sinkhorn_persistent<<<SLOTS * CPB, THREADS, SMEM_BYTES>>>(g, out);
}

// round 9
// speedup vs baseline: 3.1463x; 3.1463x over previous
#include <cuda_runtime.h>
#include <cuda_fp16.h>
#include <math.h>

#define NB 32
#define NN 1024
#define L2E 1.4426950408889634f
#define RPC 16                   // rows per CTA in iter kernel

// Static scratch (no allocation allowed). d_P = 64 MB fp16, L2-resident.
__device__ __half d_P[(size_t)NB * NN * NN];
__device__ float  d_m[NB * NN];      // per-row max of g*log2e
__device__ float  d_r[NB * NN];      // row scalings (linear domain)
__device__ float  d_c[NB * NN];      // col scalings (linear domain)
__device__ float  d_colacc[NB * NN];

// ---------------------------------------------------------------------------
__global__ __launch_bounds__(512) void init_kernel() {
    const int i = blockIdx.x * 512 + threadIdx.x;
    d_c[i] = 1.0f;
    d_colacc[i] = 0.0f;
}

// ---------------------------------------------------------------------------
// P_ij = exp2(g*L2E - M_i), M_i = row max (log2 units). Warp per row.
__global__ __launch_bounds__(256) void precompute_kernel(const float* __restrict__ g) {
    const int warp = threadIdx.x >> 5, lane = threadIdx.x & 31;
    const int row  = blockIdx.x * 8 + warp;

    const float4* gr = (const float4*)(g + (size_t)row * NN);
    float4 v[8];
    float m = -1e30f;
#pragma unroll
    for (int k = 0; k < 8; k++) {
        v[k] = gr[lane + 32 * k];
        m = fmaxf(m, fmaxf(fmaxf(v[k].x, v[k].y), fmaxf(v[k].z, v[k].w)));
    }
#pragma unroll
    for (int o = 16; o; o >>= 1)
        m = fmaxf(m, __shfl_xor_sync(0xffffffffu, m, o));
    const float mb = m * L2E;
    if (lane == 0) d_m[row] = mb;

    uint2* pr = (uint2*)(d_P + (size_t)row * NN);
#pragma unroll
    for (int k = 0; k < 8; k++) {
        const int idx = lane + 32 * k;
        __half2 h0 = __floats2half2_rn(exp2f(fmaf(v[k].x, L2E, -mb)),
                                       exp2f(fmaf(v[k].y, L2E, -mb)));
        __half2 h1 = __floats2half2_rn(exp2f(fmaf(v[k].z, L2E, -mb)),
                                       exp2f(fmaf(v[k].w, L2E, -mb)));
        uint2 u;
        u.x = *(const unsigned*)&h0;
        u.y = *(const unsigned*)&h1;
        pr[idx] = u;
    }
}

// ---------------------------------------------------------------------------
// One Sinkhorn iteration (row + col partials). 64 CTAs per batch, 16 rows each.
// Phase A (warp/row): r_i = 1/sum_j P_ij c_j; P tile cached to smem (fp16).
// Phase B (thread/2cols): colacc_j += sum_i P_ij r_i  (atomic across CTAs).
__global__ __launch_bounds__(512, 3)
void iter_kernel() {
    extern __shared__ float smem[];
    __half* s_P = (__half*)smem;                 // RPC*NN halfs = 32 KB
    float*  s_c = smem + RPC * NN / 2;           // NN floats
    float*  s_r = s_c + NN;                      // RPC floats

    const int tid  = threadIdx.x;
    const int b    = blockIdx.x >> 6;
    const int cib  = blockIdx.x & 63;
    const int warp = tid >> 5, lane = tid & 31;

    s_c[tid]       = d_c[(b << 10) + tid];
    s_c[tid + 512] = d_c[(b << 10) + tid + 512];
    __syncthreads();

    const int row = (b << 10) + cib * RPC + warp;
    const uint2*  pr  = (const uint2*)(d_P + (size_t)row * NN);
    uint2*        spr = (uint2*)(s_P + warp * NN);
    const float4* c4  = (const float4*)s_c;

    float s = 0.0f;
#pragma unroll
    for (int k = 0; k < 8; k++) {
        const int idx = lane + 32 * k;
        const uint2 pv = pr[idx];
        spr[idx] = pv;
        const float2 f0 = __half22float2(*(const __half2*)&pv.x);
        const float2 f1 = __half22float2(*(const __half2*)&pv.y);
        const float4 cv = c4[idx];
        s = fmaf(f0.x, cv.x, s);
        s = fmaf(f0.y, cv.y, s);
        s = fmaf(f1.x, cv.z, s);
        s = fmaf(f1.y, cv.w, s);
    }
#pragma unroll
    for (int o = 16; o; o >>= 1)
        s += __shfl_xor_sync(0xffffffffu, s, o);
    const float r = __fdividef(1.0f, s);
    if (lane == 0) { d_r[row] = r; s_r[warp] = r; }
    __syncthreads();

    float iv[RPC];
#pragma unroll
    for (int i = 0; i < RPC; i++) iv[i] = s_r[i];

    const __half2* sp2 = (const __half2*)s_P;
    float cx = 0.0f, cy = 0.0f;
#pragma unroll
    for (int i = 0; i < RPC; i++) {
        const float2 f = __half22float2(sp2[i * 512 + tid]);
        cx = fmaf(f.x, iv[i], cx);
        cy = fmaf(f.y, iv[i], cy);
    }
    atomicAdd(&d_colacc[(b << 10) + 2 * tid],     cx);
    atomicAdd(&d_colacc[(b << 10) + 2 * tid + 1], cy);
}

// ---------------------------------------------------------------------------
__global__ __launch_bounds__(512) void colfix_kernel() {
    const int i = blockIdx.x * 512 + threadIdx.x;
    d_c[i] = __fdividef(1.0f, d_colacc[i]);
    d_colacc[i] = 0.0f;
}

// ---------------------------------------------------------------------------
// Final pass from g in fp32 (insulates output from fp16 P error):
// out = exp2( g*L2E - M_i + log2(r_i) + log2(c_j) ). Warp per row.
__global__ __launch_bounds__(256) void final_kernel(const float* __restrict__ g,
                                                    float* __restrict__ out) {
    __shared__ float s_lc[NN];
    const int row0 = blockIdx.x * 8;
    const int b    = row0 >> 10;

    for (int t = threadIdx.x; t < NN; t += 256)
        s_lc[t] = log2f(d_c[(b << 10) + t]);
    __syncthreads();

    const int warp = threadIdx.x >> 5, lane = threadIdx.x & 31;
    const int row  = row0 + warp;
    const float rb = log2f(d_r[row]) - d_m[row];

    const float4* gr  = (const float4*)(g + (size_t)row * NN);
    const float4* lc4 = (const float4*)s_lc;
    float4*       orw = (float4*)(out + (size_t)row * NN);

#pragma unroll
    for (int k = 0; k < 8; k++) {
        const int idx = lane + 32 * k;
        const float4 gv = gr[idx];
        const float4 lv = lc4[idx];
        float4 o;
        o.x = exp2f(fmaf(gv.x, L2E, rb + lv.x));
        o.y = exp2f(fmaf(gv.y, L2E, rb + lv.y));
        o.z = exp2f(fmaf(gv.z, L2E, rb + lv.z));
        o.w = exp2f(fmaf(gv.w, L2E, rb + lv.w));
        orw[idx] = o;
    }
}

// ---------------------------------------------------------------------------
extern "C" void kernel_launch(void* const* d_in, const int* in_sizes, int n_in,
                              void* d_out, int out_size) {
    // Only the gumbel tensor matters (score projection cancels in the first
    // row normalization).
    const float* g = nullptr;
    for (int i = 0; i < n_in; i++)
        if (in_sizes[i] == NB * NN * NN) g = (const float*)d_in[i];
    float* out = (float*)d_out;

    const int SMEM_BYTES = RPC * NN * 2 + NN * 4 + RPC * 4;   // 36928
    cudaFuncSetAttribute(iter_kernel,
                         cudaFuncAttributeMaxDynamicSharedMemorySize, SMEM_BYTES);

    init_kernel<<<NB * NN / 512, 512>>>();
    precompute_kernel<<<NB * NN / 8, 256>>>(g);

    for (int it = 0; it < 20; it++) {
        iter_kernel<<<NB * (NN / RPC), 512, SMEM_BYTES>>>();
        colfix_kernel<<<NB * NN / 512, 512>>>();
    }

    final_kernel<<<NB * NN / 8, 256>>>(g, out);
}

// round 10
// speedup vs baseline: 3.3149x; 1.0536x over previous
#include <cuda_runtime.h>
#include <cuda_fp16.h>
#include <math.h>

#define NB 32
#define NN 1024
#define L2E 1.4426950408889634f
#define RPC 16                   // rows per CTA in iter kernel
#define ITERS 20

// Static scratch (no allocation allowed). d_P = 64 MB fp16, L2-resident.
__device__ __half d_P[(size_t)NB * NN * NN];
__device__ float  d_m[NB * NN];               // per-row max of g*log2e
__device__ float  d_r[NB * NN];               // row scalings (linear domain)
// Rotating column accumulators: iter k reads buf[k] (c = 1/buf[k]), writes
// buf[k+1]. buf[1..ITERS] zeroed once per launch; buf[0] unused (c==1).
__device__ float  d_colacc[ITERS + 1][NB * NN];

// ---------------------------------------------------------------------------
// Zero buf[1..ITERS]: ITERS * 32K floats.
__global__ __launch_bounds__(512) void init_kernel() {
    ((float*)&d_colacc[1][0])[blockIdx.x * 512 + threadIdx.x] = 0.0f;
}

// ---------------------------------------------------------------------------
// P_ij = exp2(g*L2E - M_i), M_i = row max (log2 units). Warp per row.
__global__ __launch_bounds__(256) void precompute_kernel(const float* __restrict__ g) {
    const int warp = threadIdx.x >> 5, lane = threadIdx.x & 31;
    const int row  = blockIdx.x * 8 + warp;

    const float4* gr = (const float4*)(g + (size_t)row * NN);
    float4 v[8];
    float m = -1e30f;
#pragma unroll
    for (int k = 0; k < 8; k++) {
        v[k] = gr[lane + 32 * k];
        m = fmaxf(m, fmaxf(fmaxf(v[k].x, v[k].y), fmaxf(v[k].z, v[k].w)));
    }
#pragma unroll
    for (int o = 16; o; o >>= 1)
        m = fmaxf(m, __shfl_xor_sync(0xffffffffu, m, o));
    const float mb = m * L2E;
    if (lane == 0) d_m[row] = mb;

    uint2* pr = (uint2*)(d_P + (size_t)row * NN);
#pragma unroll
    for (int k = 0; k < 8; k++) {
        const int idx = lane + 32 * k;
        __half2 h0 = __floats2half2_rn(exp2f(fmaf(v[k].x, L2E, -mb)),
                                       exp2f(fmaf(v[k].y, L2E, -mb)));
        __half2 h1 = __floats2half2_rn(exp2f(fmaf(v[k].z, L2E, -mb)),
                                       exp2f(fmaf(v[k].w, L2E, -mb)));
        uint2 u;
        u.x = *(const unsigned*)&h0;
        u.y = *(const unsigned*)&h1;
        pr[idx] = u;
    }
}

// ---------------------------------------------------------------------------
// One Sinkhorn iteration. 64 CTAs per batch, 16 rows each.
// Stage:   c_j = 1/buf[k][j] (or 1.0 at k==0) -> smem
// Phase A (warp/row): r_i = 1/sum_j P_ij c_j; P tile cached to smem (fp16).
// Phase B (thread/2cols): buf[k+1][j] += sum_i P_ij r_i  (atomic across CTAs).
__global__ __launch_bounds__(512, 3)
void iter_kernel(int k) {
    extern __shared__ float smem[];
    __half* s_P = (__half*)smem;                 // RPC*NN halfs = 32 KB
    float*  s_c = smem + RPC * NN / 2;           // NN floats
    float*  s_r = s_c + NN;                      // RPC floats

    const int tid  = threadIdx.x;
    const int b    = blockIdx.x >> 6;
    const int cib  = blockIdx.x & 63;
    const int warp = tid >> 5, lane = tid & 31;

    if (k == 0) {
        s_c[tid]       = 1.0f;
        s_c[tid + 512] = 1.0f;
    } else {
        const float* br = &d_colacc[k][b << 10];
        s_c[tid]       = __fdividef(1.0f, br[tid]);
        s_c[tid + 512] = __fdividef(1.0f, br[tid + 512]);
    }
    __syncthreads();

    const int row = (b << 10) + cib * RPC + warp;
    const uint2*  pr  = (const uint2*)(d_P + (size_t)row * NN);
    uint2*        spr = (uint2*)(s_P + warp * NN);
    const float4* c4  = (const float4*)s_c;

    float s = 0.0f;
#pragma unroll
    for (int kk = 0; kk < 8; kk++) {
        const int idx = lane + 32 * kk;
        const uint2 pv = pr[idx];
        spr[idx] = pv;
        const float2 f0 = __half22float2(*(const __half2*)&pv.x);
        const float2 f1 = __half22float2(*(const __half2*)&pv.y);
        const float4 cv = c4[idx];
        s = fmaf(f0.x, cv.x, s);
        s = fmaf(f0.y, cv.y, s);
        s = fmaf(f1.x, cv.z, s);
        s = fmaf(f1.y, cv.w, s);
    }
#pragma unroll
    for (int o = 16; o; o >>= 1)
        s += __shfl_xor_sync(0xffffffffu, s, o);
    const float r = __fdividef(1.0f, s);
    if (lane == 0) { d_r[row] = r; s_r[warp] = r; }
    __syncthreads();

    float iv[RPC];
#pragma unroll
    for (int i = 0; i < RPC; i++) iv[i] = s_r[i];

    const __half2* sp2 = (const __half2*)s_P;
    float cx = 0.0f, cy = 0.0f;
#pragma unroll
    for (int i = 0; i < RPC; i++) {
        const float2 f = __half22float2(sp2[i * 512 + tid]);
        cx = fmaf(f.x, iv[i], cx);
        cy = fmaf(f.y, iv[i], cy);
    }
    float* wr = &d_colacc[k + 1][b << 10];
    atomicAdd(&wr[2 * tid],     cx);
    atomicAdd(&wr[2 * tid + 1], cy);
}

// ---------------------------------------------------------------------------
// Final pass from g in fp32 (insulates output from fp16 P error):
// out = exp2( g*L2E - M_i + log2(r_i) - log2(colacc[ITERS]_j) ). Warp per row.
__global__ __launch_bounds__(256) void final_kernel(const float* __restrict__ g,
                                                    float* __restrict__ out) {
    __shared__ float s_lc[NN];
    const int row0 = blockIdx.x * 8;
    const int b    = row0 >> 10;

    for (int t = threadIdx.x; t < NN; t += 256)
        s_lc[t] = -log2f(d_colacc[ITERS][(b << 10) + t]);
    __syncthreads();

    const int warp = threadIdx.x >> 5, lane = threadIdx.x & 31;
    const int row  = row0 + warp;
    const float rb = log2f(d_r[row]) - d_m[row];

    const float4* gr  = (const float4*)(g + (size_t)row * NN);
    const float4* lc4 = (const float4*)s_lc;
    float4*       orw = (float4*)(out + (size_t)row * NN);

#pragma unroll
    for (int k = 0; k < 8; k++) {
        const int idx = lane + 32 * k;
        const float4 gv = gr[idx];
        const float4 lv = lc4[idx];
        float4 o;
        o.x = exp2f(fmaf(gv.x, L2E, rb + lv.x));
        o.y = exp2f(fmaf(gv.y, L2E, rb + lv.y));
        o.z = exp2f(fmaf(gv.z, L2E, rb + lv.z));
        o.w = exp2f(fmaf(gv.w, L2E, rb + lv.w));
        orw[idx] = o;
    }
}

// ---------------------------------------------------------------------------
extern "C" void kernel_launch(void* const* d_in, const int* in_sizes, int n_in,
                              void* d_out, int out_size) {
    // Only the gumbel tensor matters (score projection cancels in the first
    // row normalization).
    const float* g = nullptr;
    for (int i = 0; i < n_in; i++)
        if (in_sizes[i] == NB * NN * NN) g = (const float*)d_in[i];
    float* out = (float*)d_out;

    const int SMEM_BYTES = RPC * NN * 2 + NN * 4 + RPC * 4;   // 36928
    cudaFuncSetAttribute(iter_kernel,
                         cudaFuncAttributeMaxDynamicSharedMemorySize, SMEM_BYTES);

    init_kernel<<<ITERS * NB * NN / 512, 512>>>();   // zero buf[1..ITERS]
    precompute_kernel<<<NB * NN / 8, 256>>>(g);

    for (int it = 0; it < ITERS; it++)
        iter_kernel<<<NB * (NN / RPC), 512, SMEM_BYTES>>>(it);

    final_kernel<<<NB * NN / 8, 256>>>(g, out);
}

// round 11
// speedup vs baseline: 3.5705x; 1.0771x over previous
#include <cuda_runtime.h>
#include <cuda_fp16.h>
#include <math.h>

#define NB 32
#define NN 1024
#define L2E 1.4426950408889634f
#define RPC 16                   // rows per CTA
#define ITERS 20

// Static scratch (no allocation allowed). d_P = 64 MB fp16, L2-resident.
__device__ __half d_P[(size_t)NB * NN * NN];
__device__ float  d_r[NB * NN];               // row scalings (linear domain)
// Rotating column accumulators: iter k reads buf[k] (c=1/buf[k]), TMA-reduces
// into buf[k+1]. buf[1..ITERS] zeroed once per launch.
__device__ float  d_colacc[ITERS + 1][NB * NN];

// ---------------------------------------------------------------------------
__device__ __forceinline__ unsigned smem_u32(const void* p) {
    return (unsigned)__cvta_generic_to_shared(p);
}

// One 4 KB smem->global add-reduction via the TMA engine (replaces 1024
// per-thread atomics). Caller guarantees smem partials are complete.
__device__ __forceinline__ void bulk_reduce_add_4k(float* gdst, const float* ssrc) {
    asm volatile("fence.proxy.async.shared::cta;" ::: "memory");
    asm volatile(
        "cp.reduce.async.bulk.global.shared::cta.bulk_group.add.f32 [%0], [%1], %2;"
        :: "l"(gdst), "r"(smem_u32(ssrc)), "r"(NN * 4) : "memory");
    asm volatile("cp.async.bulk.commit_group;" ::: "memory");
    asm volatile("cp.async.bulk.wait_group 0;" ::: "memory");
}

// ---------------------------------------------------------------------------
// Zero buf[1..ITERS].
__global__ __launch_bounds__(512) void init_kernel() {
    ((float*)&d_colacc[1][0])[blockIdx.x * 512 + threadIdx.x] = 0.0f;
}

// ---------------------------------------------------------------------------
// Fused precompute + iteration 0. 64 CTAs/batch, 16 rows each (warp/row).
//   P_ij = exp2(g*L2E - M_i)  -> gmem (fp16) and smem tile
//   r^1_i = 1/sum_j P_ij      -> d_r
//   colacc[1]_j += sum_i P_ij r^1_i   (TMA bulk reduce)
__global__ __launch_bounds__(512)
void pre_iter0_kernel(const float* __restrict__ g) {
    extern __shared__ float smem[];
    __half* s_P = (__half*)smem;                 // RPC*NN halfs = 32 KB
    float*  s_c = smem + RPC * NN / 2;           // NN floats (col partials)
    float*  s_r = s_c + NN;                      // RPC floats

    const int tid  = threadIdx.x;
    const int b    = blockIdx.x >> 6;
    const int cib  = blockIdx.x & 63;
    const int warp = tid >> 5, lane = tid & 31;
    const int row  = (b << 10) + cib * RPC + warp;

    const float4* gr = (const float4*)(g + (size_t)row * NN);
    float4 v[8];
    float m = -1e30f;
#pragma unroll
    for (int k = 0; k < 8; k++) {
        v[k] = gr[lane + 32 * k];
        m = fmaxf(m, fmaxf(fmaxf(v[k].x, v[k].y), fmaxf(v[k].z, v[k].w)));
    }
#pragma unroll
    for (int o = 16; o; o >>= 1)
        m = fmaxf(m, __shfl_xor_sync(0xffffffffu, m, o));
    const float mb = m * L2E;

    uint2* pg = (uint2*)(d_P + (size_t)row * NN);
    uint2* sp = (uint2*)(s_P + warp * NN);
    float  s  = 0.0f;
#pragma unroll
    for (int k = 0; k < 8; k++) {
        const int idx = lane + 32 * k;
        const float ex = exp2f(fmaf(v[k].x, L2E, -mb));
        const float ey = exp2f(fmaf(v[k].y, L2E, -mb));
        const float ez = exp2f(fmaf(v[k].z, L2E, -mb));
        const float ew = exp2f(fmaf(v[k].w, L2E, -mb));
        __half2 h0 = __floats2half2_rn(ex, ey);
        __half2 h1 = __floats2half2_rn(ez, ew);
        uint2 u;
        u.x = *(const unsigned*)&h0;
        u.y = *(const unsigned*)&h1;
        pg[idx] = u;
        sp[idx] = u;
        s += (ex + ey) + (ez + ew);
    }
#pragma unroll
    for (int o = 16; o; o >>= 1)
        s += __shfl_xor_sync(0xffffffffu, s, o);
    const float r = __fdividef(1.0f, s);
    if (lane == 0) { d_r[row] = r; s_r[warp] = r; }
    __syncthreads();

    float iv[RPC];
#pragma unroll
    for (int i = 0; i < RPC; i++) iv[i] = s_r[i];

    const __half2* sp2 = (const __half2*)s_P;
    float cx = 0.0f, cy = 0.0f;
#pragma unroll
    for (int i = 0; i < RPC; i++) {
        const float2 f = __half22float2(sp2[i * 512 + tid]);
        cx = fmaf(f.x, iv[i], cx);
        cy = fmaf(f.y, iv[i], cy);
    }
    ((float2*)s_c)[tid] = make_float2(cx, cy);
    __syncthreads();

    if (tid == 0) bulk_reduce_add_4k(&d_colacc[1][b << 10], s_c);
}

// ---------------------------------------------------------------------------
// Sinkhorn iteration k (k = 1..19). 64 CTAs/batch, 16 rows each.
//   c_j = 1/colacc[k][j] -> smem
//   r_i = 1/sum_j P_ij c_j  (warp/row, P tile cached to smem)
//   colacc[k+1]_j += sum_i P_ij r_i   (TMA bulk reduce)
__global__ __launch_bounds__(512, 3)
void iter_kernel(int k) {
    extern __shared__ float smem[];
    __half* s_P = (__half*)smem;
    float*  s_c = smem + RPC * NN / 2;
    float*  s_r = s_c + NN;

    const int tid  = threadIdx.x;
    const int b    = blockIdx.x >> 6;
    const int cib  = blockIdx.x & 63;
    const int warp = tid >> 5, lane = tid & 31;

    {
        const float* br = &d_colacc[k][b << 10];
        s_c[tid]       = __fdividef(1.0f, br[tid]);
        s_c[tid + 512] = __fdividef(1.0f, br[tid + 512]);
    }
    __syncthreads();

    const int row = (b << 10) + cib * RPC + warp;
    const uint2*  pr  = (const uint2*)(d_P + (size_t)row * NN);
    uint2*        spr = (uint2*)(s_P + warp * NN);
    const float4* c4  = (const float4*)s_c;

    float s = 0.0f;
#pragma unroll
    for (int kk = 0; kk < 8; kk++) {
        const int idx = lane + 32 * kk;
        const uint2 pv = __ldcg(&pr[idx]);
        spr[idx] = pv;
        const float2 f0 = __half22float2(*(const __half2*)&pv.x);
        const float2 f1 = __half22float2(*(const __half2*)&pv.y);
        const float4 cv = c4[idx];
        s = fmaf(f0.x, cv.x, s);
        s = fmaf(f0.y, cv.y, s);
        s = fmaf(f1.x, cv.z, s);
        s = fmaf(f1.y, cv.w, s);
    }
#pragma unroll
    for (int o = 16; o; o >>= 1)
        s += __shfl_xor_sync(0xffffffffu, s, o);
    const float r = __fdividef(1.0f, s);
    if (lane == 0) { d_r[row] = r; s_r[warp] = r; }
    __syncthreads();

    float iv[RPC];
#pragma unroll
    for (int i = 0; i < RPC; i++) iv[i] = s_r[i];

    const __half2* sp2 = (const __half2*)s_P;
    float cx = 0.0f, cy = 0.0f;
#pragma unroll
    for (int i = 0; i < RPC; i++) {
        const float2 f = __half22float2(sp2[i * 512 + tid]);
        cx = fmaf(f.x, iv[i], cx);
        cy = fmaf(f.y, iv[i], cy);
    }
    ((float2*)s_c)[tid] = make_float2(cx, cy);
    __syncthreads();

    if (tid == 0) bulk_reduce_add_4k(&d_colacc[k + 1][b << 10], s_c);
}

// ---------------------------------------------------------------------------
// Final: out_ij = P_ij * r_i * c_j with c_j = 1/colacc[ITERS][j].
// P read from (hot) L2 in fp16 — no exp2, no g re-read. Warp per row.
__global__ __launch_bounds__(256) void final_kernel(float* __restrict__ out) {
    __shared__ float s_ci[NN];
    const int row0 = blockIdx.x * 8;
    const int b    = row0 >> 10;

    for (int t = threadIdx.x; t < NN; t += 256)
        s_ci[t] = __fdividef(1.0f, d_colacc[ITERS][(b << 10) + t]);
    __syncthreads();

    const int warp = threadIdx.x >> 5, lane = threadIdx.x & 31;
    const int row  = row0 + warp;
    const float rv = d_r[row];

    const uint2*  pr  = (const uint2*)(d_P + (size_t)row * NN);
    const float4* ci4 = (const float4*)s_ci;
    float4*       orw = (float4*)(out + (size_t)row * NN);

#pragma unroll
    for (int k = 0; k < 8; k++) {
        const int idx = lane + 32 * k;
        const uint2 pv = __ldcg(&pr[idx]);
        const float2 f0 = __half22float2(*(const __half2*)&pv.x);
        const float2 f1 = __half22float2(*(const __half2*)&pv.y);
        const float4 cv = ci4[idx];
        float4 o;
        o.x = f0.x * rv * cv.x;
        o.y = f0.y * rv * cv.y;
        o.z = f1.x * rv * cv.z;
        o.w = f1.y * rv * cv.w;
        orw[idx] = o;
    }
}

// ---------------------------------------------------------------------------
extern "C" void kernel_launch(void* const* d_in, const int* in_sizes, int n_in,
                              void* d_out, int out_size) {
    // Only the gumbel tensor matters (score projection cancels in the first
    // row normalization).
    const float* g = nullptr;
    for (int i = 0; i < n_in; i++)
        if (in_sizes[i] == NB * NN * NN) g = (const float*)d_in[i];
    float* out = (float*)d_out;

    const int SMEM_BYTES = RPC * NN * 2 + NN * 4 + RPC * 4;   // 36928
    cudaFuncSetAttribute(pre_iter0_kernel,
                         cudaFuncAttributeMaxDynamicSharedMemorySize, SMEM_BYTES);
    cudaFuncSetAttribute(iter_kernel,
                         cudaFuncAttributeMaxDynamicSharedMemorySize, SMEM_BYTES);

    init_kernel<<<ITERS * NB * NN / 512, 512>>>();          // zero buf[1..20]
    pre_iter0_kernel<<<NB * (NN / RPC), 512, SMEM_BYTES>>>(g);  // P + iter 0

    for (int it = 1; it < ITERS; it++)
        iter_kernel<<<NB * (NN / RPC), 512, SMEM_BYTES>>>(it);

    final_kernel<<<NB * NN / 8, 256>>>(out);
}